// round 5
// baseline (speedup 1.0000x reference)
#include <cuda_runtime.h>
#include <cstdint>

// Block-diagonal grouped conv2d: 64 groups, 4 in-ch -> 4 out-ch per group, 3x3, pad 1.
// v5: persistent (b,head) CTAs over 8 row-tiles, double-buffered cp.async
//     prefetch (DRAM latency fully overlapped with compute), swizzled smem,
//     shuffle edges, packed f32x2 FMA. 2 CTAs/SM.

#define TY 16
#define SROW_P 188                   // phys floats per row
#define PLANE_P (18 * SROW_P)        // 3384
#define S_BUF (4 * PLANE_P)          // floats per buffer (13536)
#define THREADS 256
#define H 128
#define W 128
#define PLANE (H * W)
#define NT 8                         // row-tiles per CTA
#define SMEM_BYTES ((2 * S_BUF + 2 * 144 + 8) * 4)

typedef unsigned long long u64;

__device__ __forceinline__ u64 pk(float lo, float hi) {
    u64 r; asm("mov.b64 %0, {%1, %2};" : "=l"(r) : "f"(lo), "f"(hi)); return r;
}
__device__ __forceinline__ void ffma2(u64 &d, u64 a, u64 b) {
    asm("fma.rn.f32x2 %0, %1, %2, %0;" : "+l"(d) : "l"(a), "l"(b));
}
__device__ __forceinline__ void cpasync16(uint32_t saddr, const float* g, bool pred) {
    int sz = pred ? 16 : 0;
    asm volatile("cp.async.cg.shared.global [%0], [%1], 16, %2;\n"
                 :: "r"(saddr), "l"(g), "r"(sz));
}
__device__ __forceinline__ void cp_commit() {
    asm volatile("cp.async.commit_group;\n");
}
template <int N>
__device__ __forceinline__ void cp_wait() {
    asm volatile("cp.async.wait_group %0;\n" :: "n"(N));
}

union F4 { float4 f; ulonglong2 u; };

__global__ __launch_bounds__(THREADS, 2)
void bdconv_kernel(const float* __restrict__ x, const float* __restrict__ w,
                   const float* __restrict__ bias, float* __restrict__ out) {
    extern __shared__ __align__(16) float smem[];
    float* s_in   = smem;                         // 2 buffers
    u64*   s_w    = (u64*)(smem + 2 * S_BUF);     // [ci][ky][kx][co], dup halves
    float* s_bias = (float*)(s_w + 144);

    const int blk  = blockIdx.x;                  // b*64 + head
    const int head = blk & 63;
    const int b    = blk >> 6;
    const int tid  = threadIdx.x;
    const int wrp  = tid >> 5;
    const int lane = tid & 31;

    // ---- weights (dup into f32x2 halves) + bias, once per CTA ----
    if (tid < 144) {
        const int co  = tid / 36;
        const int rem = tid % 36;
        const int ci  = rem / 9;
        const int t   = rem % 9;
        const float wv = w[((head * 4 + co) * 4 + ci) * 9 + t];
        s_w[(ci * 9 + t) * 4 + co] = pk(wv, wv);
    }
    if (tid < 4) s_bias[tid] = bias[head * 4 + tid];

    // ---- staging geometry: 2 warps per ci-plane, 9 rows each; lane->chunk perm ----
    const int ci_s = wrp >> 1;
    const int r0s  = (wrp & 1) * 9;
    int x0, sig;
    if (lane < 16) { x0 = lane << 3;              sig = 3 * lane; }
    else           { x0 = ((lane - 16) << 3) + 4; sig = 3 * (lane - 16) + 1; }
    const float* xpl = x + ((long long)b * 256 + head) * PLANE + ci_s * (64 * PLANE);
    const uint32_t s_stage =
        (uint32_t)__cvta_generic_to_shared(s_in) + (uint32_t)(ci_s * PLANE_P + (sig << 2)) * 4u;

    // prefetch tile 0 into buffer 0
    {
        #pragma unroll
        for (int k = 0; k < 9; k++) {
            const int r = r0s + k;
            const int y = -1 + r;
            const bool ok = (y >= 0);             // tile 0: y < H always
            const int yc = ok ? y : 0;
            cpasync16(s_stage + (uint32_t)(r * SROW_P) * 4u, xpl + yc * W + x0, ok);
        }
        cp_commit();
    }

    // ---- compute geometry ----
    const int r  = tid >> 4;            // row in tile
    const int j  = tid & 15;            // pixel octet, x = 8j..8j+7
    const int cbase = r * SROW_P + 12 * j;
    const float* bufP = s_in + cbase;
    const float* bufQ = s_in + S_BUF + cbase;

    const u64 bp0 = pk(s_bias[0], s_bias[0]);   // note: s_bias written by tid<4,
    // (read after first __syncthreads below; keep lazily via s_bias reads then)

    float* obase0 = out + (((long long)b * 256 + head) * H) * W + (j << 3);

    #pragma unroll 1
    for (int t = 0; t < NT; t++) {
        // prefetch next tile into the other buffer
        if (t + 1 < NT) {
            const uint32_t sb = s_stage + (uint32_t)(((t + 1) & 1) * S_BUF) * 4u;
            const int y0n = (t + 1) * TY;
            #pragma unroll
            for (int k = 0; k < 9; k++) {
                const int rr = r0s + k;
                const int y  = y0n - 1 + rr;
                const bool ok = (y >= 0) && (y < H);
                const int yc = ok ? y : 0;
                cpasync16(sb + (uint32_t)(rr * SROW_P) * 4u, xpl + yc * W + x0, ok);
            }
        }
        cp_commit();
        cp_wait<1>();                   // tile t resident
        __syncthreads();

        const float* sp = (t & 1) ? bufQ : bufP;

        u64 acc[4][4];
        #pragma unroll
        for (int co = 0; co < 4; co++) {
            const float bv = s_bias[co];
            const u64 bpp = pk(bv, bv);
            #pragma unroll
            for (int q = 0; q < 4; q++) acc[co][q] = bpp;
        }

        #pragma unroll
        for (int ci = 0; ci < 4; ci++) {
            #pragma unroll
            for (int ky = 0; ky < 3; ky++) {
                const int imm = ci * PLANE_P + ky * SROW_P;
                F4 B, C;
                B.f = *(const float4*)(sp + imm);
                C.f = *(const float4*)(sp + imm + 4);

                float A = __shfl_up_sync(0xffffffffu, C.f.w, 1);
                float D = __shfl_down_sync(0xffffffffu, B.f.x, 1);
                if (j == 0)  A = 0.0f;
                if (j == 15) D = 0.0f;

                u64 p[9];
                p[0] = pk(A,     B.f.x);
                p[1] = B.u.x;
                p[2] = pk(B.f.y, B.f.z);
                p[3] = B.u.y;
                p[4] = pk(B.f.w, C.f.x);
                p[5] = C.u.x;
                p[6] = pk(C.f.y, C.f.z);
                p[7] = C.u.y;
                p[8] = pk(C.f.w, D);

                const ulonglong2* wp = (const ulonglong2*)(s_w + (ci * 9 + ky * 3) * 4);
                ulonglong2 wv[6];
                #pragma unroll
                for (int q = 0; q < 6; q++) wv[q] = wp[q];

                #pragma unroll
                for (int q = 0; q < 4; q++)
                    #pragma unroll
                    for (int kx = 0; kx < 3; kx++) {
                        const u64 in = p[2 * q + kx];
                        ffma2(acc[0][q], wv[kx * 2 + 0].x, in);
                        ffma2(acc[1][q], wv[kx * 2 + 0].y, in);
                        ffma2(acc[2][q], wv[kx * 2 + 1].x, in);
                        ffma2(acc[3][q], wv[kx * 2 + 1].y, in);
                    }
            }
        }

        // store 2x STG.128 per co
        float* ob = obase0 + (long long)(t * TY + r) * W;
        #pragma unroll
        for (int co = 0; co < 4; co++) {
            ulonglong2* dst = (ulonglong2*)(ob + (long long)co * (64 * PLANE));
            ulonglong2 s0, s1;
            s0.x = acc[co][0]; s0.y = acc[co][1];
            s1.x = acc[co][2]; s1.y = acc[co][3];
            dst[0] = s0;
            dst[1] = s1;
        }
        __syncthreads();               // all reads of buf[t&1] done before reuse
    }
    (void)bp0;
}

extern "C" void kernel_launch(void* const* d_in, const int* in_sizes, int n_in,
                              void* d_out, int out_size) {
    const float* x    = (const float*)d_in[0];
    const float* w    = (const float*)d_in[1];
    const float* bias = (const float*)d_in[2];
    float* out        = (float*)d_out;
    (void)in_sizes; (void)n_in; (void)out_size;
    cudaFuncSetAttribute(bdconv_kernel,
                         cudaFuncAttributeMaxDynamicSharedMemorySize, SMEM_BYTES);
    bdconv_kernel<<<32 * 64, THREADS, SMEM_BYTES>>>(x, w, bias, out);
}

// round 6
// speedup vs baseline: 1.4222x; 1.4222x over previous
#include <cuda_runtime.h>

// Block-diagonal grouped conv2d: 64 groups, 4 in-ch -> 4 out-ch per group, 3x3, pad 1.
// x:   (32, 256, 128, 128) fp32, channel index = ci*64 + head
// w:   (64, 4, 4, 3, 3)          w[head][co][ci][ky][kx]
// b:   (64, 4)
// out: (32, 256, 128, 128) fp32, channel index = co*64 + head
//
// v6 = v4 inner loop, re-shaped for occupancy: 128-thread CTAs, TY=8 row
//      tiles, 7 CTAs/SM (reg-fit 73), swizzled conflict-free smem, shuffle
//      edges, packed f32x2 FMA.

#define TY 8
#define SROWS (TY + 2)               // 10
#define SROW_P 188                   // phys floats per row (swizzle pad)
#define PLANE_P (SROWS * SROW_P)     // 1880
#define S_IN_FLOATS (4 * PLANE_P)    // 7520
#define THREADS 128
#define H 128
#define W 128
#define PLANE (H * W)
#define SMEM_BYTES ((S_IN_FLOATS + 2 * 144 + 4) * 4)

typedef unsigned long long u64;

__device__ __forceinline__ u64 pk(float lo, float hi) {
    u64 r; asm("mov.b64 %0, {%1, %2};" : "=l"(r) : "f"(lo), "f"(hi)); return r;
}
// d += a*b  (packed 2x fp32)
__device__ __forceinline__ void ffma2(u64 &d, u64 a, u64 b) {
    asm("fma.rn.f32x2 %0, %1, %2, %0;" : "+l"(d) : "l"(a), "l"(b));
}

union F4 { float4 f; ulonglong2 u; };

__global__ __launch_bounds__(THREADS, 7)
void bdconv_kernel(const float* __restrict__ x, const float* __restrict__ w,
                   const float* __restrict__ bias, float* __restrict__ out) {
    extern __shared__ __align__(16) float smem[];
    float* s_in   = smem;                        // [ci][r][phys-col]
    u64*   s_w    = (u64*)(smem + S_IN_FLOATS);  // [ci][ky][kx][co], dup halves
    float* s_bias = (float*)(s_w + 144);

    const int blk  = blockIdx.x;
    const int tile = blk & 15;          // 16 row-tiles of 8
    const int head = (blk >> 4) & 63;
    const int b    = blk >> 10;
    const int y0   = tile * TY;
    const int tid  = threadIdx.x;
    const int wrp  = tid >> 5;
    const int lane = tid & 31;

    // ---- stage weights (duplicated into f32x2 lanes) + bias ----
    for (int t = tid; t < 144; t += THREADS) {
        const int co  = t / 36;
        const int rem = t % 36;
        const int ci  = rem / 9;
        const int tt  = rem % 9;        // ky*3+kx
        const float wv = w[((head * 4 + co) * 4 + ci) * 9 + tt];
        s_w[(ci * 9 + tt) * 4 + co] = pk(wv, wv);
    }
    if (tid < 4) s_bias[tid] = bias[head * 4 + tid];

    // ---- stage input: 4 warps, 10 warp-rows each (40 = 4ci x 10 rows) ----
    // lane->chunk permutation keeps STS.128 conflict-free under the swizzle:
    //   lanes 0-15  -> even chunks  (phys chunk sigma = 3l)
    //   lanes 16-31 -> odd  chunks  (phys chunk sigma = 3m+1)
    int x0, sig;
    if (lane < 16) { x0 = lane << 3;              sig = 3 * lane; }
    else           { x0 = ((lane - 16) << 3) + 4; sig = 3 * (lane - 16) + 1; }
    const float* xb = x + ((long long)b * 256 + head) * PLANE;   // ci stride 64*PLANE
    #pragma unroll
    for (int k = 0; k < 10; k++) {
        const int rr = wrp + (k << 2);            // 0..39
        const int ci = rr / SROWS;
        const int r  = rr - ci * SROWS;
        const int y  = y0 - 1 + r;
        float4 v = make_float4(0.f, 0.f, 0.f, 0.f);
        if (y >= 0 && y < H)
            v = *(const float4*)(xb + ci * (64 * PLANE) + y * W + x0);
        *(float4*)(s_in + ci * PLANE_P + r * SROW_P + (sig << 2)) = v;
    }
    __syncthreads();

    // ---- compute: each thread = 8 pixels x 4 out-channels ----
    const int r  = tid >> 4;           // row within tile, 0..7
    const int j  = tid & 15;           // pixel-octet index, x = 8j..8j+7
    const int base = r * SROW_P + 12 * j;   // phys(8j) = 12j

    u64 acc[4][4];                     // [co][pixel-pair]
    #pragma unroll
    for (int co = 0; co < 4; co++) {
        const float bv = s_bias[co];
        const u64 bp = pk(bv, bv);
        #pragma unroll
        for (int q = 0; q < 4; q++) acc[co][q] = bp;
    }

    #pragma unroll
    for (int ci = 0; ci < 4; ci++) {
        #pragma unroll
        for (int ky = 0; ky < 3; ky++) {
            const int imm = ci * PLANE_P + ky * SROW_P;   // compile-time
            F4 B, C;
            B.f = *(const float4*)(s_in + imm + base);
            C.f = *(const float4*)(s_in + imm + base + 4);

            // window edges from neighbor lanes (zero at x-boundaries)
            float A = __shfl_up_sync(0xffffffffu, C.f.w, 1);
            float D = __shfl_down_sync(0xffffffffu, B.f.x, 1);
            if (j == 0)  A = 0.0f;
            if (j == 15) D = 0.0f;

            // 9 adjacent pairs of window x(8j-1 .. 8j+8)
            u64 p[9];
            p[0] = pk(A,     B.f.x);
            p[1] = B.u.x;
            p[2] = pk(B.f.y, B.f.z);
            p[3] = B.u.y;
            p[4] = pk(B.f.w, C.f.x);
            p[5] = C.u.x;
            p[6] = pk(C.f.y, C.f.z);
            p[7] = C.u.y;
            p[8] = pk(C.f.w, D);

            // weights: 6 x LDS.128 uniform broadcast -> [kx][co]
            const ulonglong2* wp = (const ulonglong2*)(s_w + (ci * 9 + ky * 3) * 4);
            ulonglong2 wv[6];
            #pragma unroll
            for (int t = 0; t < 6; t++) wv[t] = wp[t];

            // 48 packed FMAs
            #pragma unroll
            for (int q = 0; q < 4; q++)
                #pragma unroll
                for (int kx = 0; kx < 3; kx++) {
                    const u64 in = p[2 * q + kx];
                    ffma2(acc[0][q], wv[kx * 2 + 0].x, in);
                    ffma2(acc[1][q], wv[kx * 2 + 0].y, in);
                    ffma2(acc[2][q], wv[kx * 2 + 1].x, in);
                    ffma2(acc[3][q], wv[kx * 2 + 1].y, in);
                }
        }
    }

    // ---- store: coalesced 2x STG.128 per co ----
    const int y = y0 + r;
    float* obase = out + (((long long)b * 256 + head) * H + y) * W + (j << 3);
    #pragma unroll
    for (int co = 0; co < 4; co++) {
        ulonglong2* dst = (ulonglong2*)(obase + (long long)co * (64 * PLANE));
        ulonglong2 s0, s1;
        s0.x = acc[co][0]; s0.y = acc[co][1];
        s1.x = acc[co][2]; s1.y = acc[co][3];
        dst[0] = s0;
        dst[1] = s1;
    }
}

extern "C" void kernel_launch(void* const* d_in, const int* in_sizes, int n_in,
                              void* d_out, int out_size) {
    const float* x    = (const float*)d_in[0];
    const float* w    = (const float*)d_in[1];
    const float* bias = (const float*)d_in[2];
    float* out        = (float*)d_out;
    (void)in_sizes; (void)n_in; (void)out_size;
    cudaFuncSetAttribute(bdconv_kernel,
                         cudaFuncAttributeMaxDynamicSharedMemorySize, SMEM_BYTES);
    bdconv_kernel<<<32 * 64 * 16, THREADS, SMEM_BYTES>>>(x, w, bias, out);
}